// round 9
// baseline (speedup 1.0000x reference)
#include <cuda_runtime.h>
#include <cuda_bf16.h>
#include <cstdint>

#define NMAX 50000
#define EMAX 800000
#define FD   128

// ---------------- scratch (device globals) ---------------------------------
__device__ float g_agg1[NMAX * FD];
__device__ float g_x1  [NMAX * FD];
__device__ float g_agg2[NMAX * FD];
__device__ int   g_cnti[NMAX];
__device__ int   g_off [NMAX + 1];
__device__ int   g_cur [NMAX];
__device__ int   g_csr [EMAX];
// weights: 3 layers x [128 out x 256 k]  (k = [Wl | Wr]), bf16 hi/lo split
__device__ __nv_bfloat16 g_wh[3 * 128 * 256];
__device__ __nv_bfloat16 g_wl[3 * 128 * 256];

// ---------------- CSR build -------------------------------------------------
__global__ void zero_cnt(int n) {
    int i = blockIdx.x * blockDim.x + threadIdx.x;
    if (i < n) g_cnti[i] = 0;
}

__global__ void hist_kernel(const int* __restrict__ dst, int E, int n) {
    int e = blockIdx.x * blockDim.x + threadIdx.x;
    if (e < E) {
        int d = dst[e];
        if ((unsigned)d < (unsigned)n) atomicAdd(&g_cnti[d], 1);
    }
}

// fused: per-block prefix base (re-summed) + in-block exclusive scan
__global__ void offsets2_kernel(int n) {
    __shared__ int buf[256];
    int tid = threadIdx.x;
    int blk = blockIdx.x;

    // base = sum of counts in all preceding blocks
    int partial = 0;
    int limit = blk * 256;
    for (int j = tid; j < limit; j += 256) partial += __ldg(&g_cnti[j]);
    buf[tid] = partial;
    __syncthreads();
    for (int s = 128; s > 0; s >>= 1) {
        if (tid < s) buf[tid] += buf[tid + s];
        __syncthreads();
    }
    int base = buf[0];
    __syncthreads();

    // local exclusive scan
    int i = blk * 256 + tid;
    int c = (i < n) ? g_cnti[i] : 0;
    buf[tid] = c;
    __syncthreads();
    for (int s = 1; s < 256; s <<= 1) {
        int t = (tid >= s) ? buf[tid - s] : 0;
        __syncthreads();
        buf[tid] += t;
        __syncthreads();
    }
    int off = base + buf[tid] - c;
    if (i < n) { g_off[i] = off; g_cur[i] = off; }
    if (i == n - 1) g_off[n] = off + c;
}

__global__ void fill_kernel(const int* __restrict__ src,
                            const int* __restrict__ dst, int E, int n) {
    int e = blockIdx.x * blockDim.x + threadIdx.x;
    if (e < E) {
        int d = dst[e], s = src[e];
        if ((unsigned)d < (unsigned)n && (unsigned)s < (unsigned)n) {
            int pos = atomicAdd(&g_cur[d], 1);
            g_csr[pos] = s;
        }
    }
}

// ---------------- gather aggregation (mean folded in) ------------------------
__global__ void gather_kernel(const float* __restrict__ feat,
                              float* __restrict__ agg, int n) {
    int gt = blockIdx.x * blockDim.x + threadIdx.x;
    int node = gt >> 5, lane = gt & 31;
    if (node >= n) return;
    int beg = __ldg(&g_off[node]);
    int end = __ldg(&g_off[node + 1]);
    float4 acc = make_float4(0.f, 0.f, 0.f, 0.f);
    int j = beg;
    for (; j + 4 <= end; j += 4) {
        int s0 = __ldg(&g_csr[j + 0]);
        int s1 = __ldg(&g_csr[j + 1]);
        int s2 = __ldg(&g_csr[j + 2]);
        int s3 = __ldg(&g_csr[j + 3]);
        float4 v0 = __ldg(((const float4*)(feat + (size_t)s0 * FD)) + lane);
        float4 v1 = __ldg(((const float4*)(feat + (size_t)s1 * FD)) + lane);
        float4 v2 = __ldg(((const float4*)(feat + (size_t)s2 * FD)) + lane);
        float4 v3 = __ldg(((const float4*)(feat + (size_t)s3 * FD)) + lane);
        acc.x += v0.x + v1.x + v2.x + v3.x;
        acc.y += v0.y + v1.y + v2.y + v3.y;
        acc.z += v0.z + v1.z + v2.z + v3.z;
        acc.w += v0.w + v1.w + v2.w + v3.w;
    }
    for (; j < end; j++) {
        int s = __ldg(&g_csr[j]);
        float4 v = __ldg(((const float4*)(feat + (size_t)s * FD)) + lane);
        acc.x += v.x; acc.y += v.y; acc.z += v.z; acc.w += v.w;
    }
    int deg = end - beg;
    float sc = (deg > 0) ? (1.0f / (float)deg) : 0.0f;
    acc.x *= sc; acc.y *= sc; acc.z *= sc; acc.w *= sc;
    *(((float4*)(agg + (size_t)node * FD)) + lane) = acc;
}

// ---------------- weight split ----------------------------------------------
__device__ __forceinline__ void split2(float a, float b, uint32_t& hi, uint32_t& lo) {
    __nv_bfloat16 ah = __float2bfloat16(a);
    __nv_bfloat16 bh = __float2bfloat16(b);
    __nv_bfloat162 h2 = __nv_bfloat162(ah, bh);
    __nv_bfloat162 l2 = __nv_bfloat162(__float2bfloat16(a - __bfloat162float(ah)),
                                       __float2bfloat16(b - __bfloat162float(bh)));
    hi = *(uint32_t*)&h2;
    lo = *(uint32_t*)&l2;
}

__device__ __forceinline__ void split_store(float v, __nv_bfloat16* h, __nv_bfloat16* l) {
    __nv_bfloat16 hb = __float2bfloat16(v);
    *h = hb;
    *l = __float2bfloat16(v - __bfloat162float(hb));
}

__global__ void conv_w(const float* W1l, const float* W1r,
                       const float* W2l, const float* W2r,
                       const float* W3l, const float* W3r) {
    int q = blockIdx.x * blockDim.x + threadIdx.x;
    if (q >= 3 * 128 * 64) return;
    int L = q / 8192, rem = q % 8192;
    int o = rem >> 6, kq = (rem & 63) << 2;
    const float* Wl = (L == 0) ? W1l : (L == 1) ? W2l : W3l;
    const float* Wr = (L == 0) ? W1r : (L == 1) ? W2r : W3r;
    const float* sp = (kq < 128) ? (Wl + o * 128 + kq) : (Wr + o * 128 + kq - 128);
    float4 v = __ldg((const float4*)sp);
    size_t out = (size_t)L * 32768 + (size_t)o * 256 + kq;
    split_store(v.x, g_wh + out + 0, g_wl + out + 0);
    split_store(v.y, g_wh + out + 1, g_wl + out + 1);
    split_store(v.z, g_wh + out + 2, g_wl + out + 2);
    split_store(v.w, g_wh + out + 3, g_wl + out + 3);
}

// ---------------- mma.sync helpers ------------------------------------------
__device__ __forceinline__ uint32_t smem_u32(const void* p) {
    uint32_t a;
    asm("{ .reg .u64 t; cvta.to.shared.u64 t, %1; cvt.u32.u64 %0, t; }" : "=r"(a) : "l"(p));
    return a;
}

__device__ __forceinline__ void ldm_x4(uint32_t* r, uint32_t addr) {
    asm volatile("ldmatrix.sync.aligned.m8n8.x4.shared.b16 {%0,%1,%2,%3}, [%4];"
                 : "=r"(r[0]), "=r"(r[1]), "=r"(r[2]), "=r"(r[3]) : "r"(addr));
}

__device__ __forceinline__ void mma_bf16(float* d, const uint32_t* a, const uint32_t* b) {
    asm volatile("mma.sync.aligned.m16n8k16.row.col.f32.bf16.bf16.f32 "
                 "{%0,%1,%2,%3}, {%4,%5,%6,%7}, {%8,%9}, {%0,%1,%2,%3};"
                 : "+f"(d[0]), "+f"(d[1]), "+f"(d[2]), "+f"(d[3])
                 : "r"(a[0]), "r"(a[1]), "r"(a[2]), "r"(a[3]), "r"(b[0]), "r"(b[1]));
}

// ---- layer-1 GEMM: K-chunk=64, smem 73.7KB, 2 CTAs/SM ----------------------
#define PS2  72
#define AB2  (128 * PS2 * 2)          // 18432 bytes per 128x64 bf16 buffer
#define Q1_AH 0
#define Q1_AL (AB2)
#define Q1_WH (2 * AB2)
#define Q1_WL (3 * AB2)
#define Q1_SMEM (4 * AB2)             // 73728

__global__ void __launch_bounds__(256, 2)
gemm1(const float* __restrict__ Aagg, const float* __restrict__ Aself,
      const __nv_bfloat16* __restrict__ Whi, const __nv_bfloat16* __restrict__ Wlo,
      const float* __restrict__ bias, float* __restrict__ outF, int n) {
    extern __shared__ __align__(16) char smem[];
    uint32_t sb = smem_u32(smem);
    int tid = threadIdx.x, wid = tid >> 5, lane = tid & 31;
    int base_row = blockIdx.x * 128;

    int m_warp = (wid & 3) * 32;
    int n_warp = (wid >> 2) * 64;

    float acc[2][8][4];
#pragma unroll
    for (int i = 0; i < 2; i++)
#pragma unroll
        for (int j = 0; j < 8; j++)
#pragma unroll
            for (int k = 0; k < 4; k++) acc[i][j][k] = 0.0f;

    int g = lane >> 3, lr = lane & 7;
    int a_row = (g & 1) * 8 + lr;
    int a_col = (g >> 1) * 8;

    for (int kc2 = 0; kc2 < 4; kc2++) {
        if (kc2) __syncthreads();
        const float* S = (kc2 < 2) ? Aagg : Aself;
        int colbase = (kc2 & 1) * 64;

        // ---- A: 128 rows x 64 fp32 cols; split in-register ----
#pragma unroll
        for (int i = 0; i < 8; i++) {
            int q = tid + i * 256;            // 0..2047 float4 slots (16/row)
            int row = q >> 4;
            int c4 = (q & 15) << 2;
            int gr = base_row + row;
            float4 v = (gr < n) ? __ldg((const float4*)(S + (size_t)gr * FD + colbase + c4))
                                : make_float4(0.f, 0.f, 0.f, 0.f);
            uint32_t h0, l0, h1, l1;
            split2(v.x, v.y, h0, l0);
            split2(v.z, v.w, h1, l1);
            uint32_t so = (uint32_t)(row * PS2 + c4) * 2;
            *(uint2*)(smem + Q1_AH + so) = make_uint2(h0, h1);
            *(uint2*)(smem + Q1_AL + so) = make_uint2(l0, l1);
        }
        // ---- W: 128 rows x 64 bf16 cols (hi+lo) ----
#pragma unroll
        for (int i = 0; i < 4; i++) {
            int q = tid + i * 256;            // 0..1023 uint4 slots (8/row)
            int row = q >> 3;
            int c8 = (q & 7) * 8;
            size_t gW = (size_t)row * 256 + kc2 * 64 + c8;
            uint32_t so = (uint32_t)(row * PS2 + c8) * 2;
            *(uint4*)(smem + Q1_WH + so) = *(const uint4*)(Whi + gW);
            *(uint4*)(smem + Q1_WL + so) = *(const uint4*)(Wlo + gW);
        }
        __syncthreads();

        // ---- compute (B regs loaded per n-pair to cap register pressure) --
#pragma unroll
        for (int k16 = 0; k16 < 4; k16++) {
            int kb = k16 * 16;
            uint32_t ah[2][4], al[2][4];
#pragma unroll
            for (int mi = 0; mi < 2; mi++) {
                uint32_t ad = sb + (uint32_t)((m_warp + mi * 16 + a_row) * PS2 + kb + a_col) * 2;
                ldm_x4(ah[mi], Q1_AH + ad);
                ldm_x4(al[mi], Q1_AL + ad);
            }
#pragma unroll
            for (int np = 0; np < 4; np++) {
                uint32_t bd = sb + (uint32_t)((n_warp + np * 16 + a_row) * PS2 + kb + a_col) * 2;
                uint32_t th[4], tl[4];
                ldm_x4(th, Q1_WH + bd);
                ldm_x4(tl, Q1_WL + bd);
                uint32_t bh0[2] = {th[0], th[2]}, bh1[2] = {th[1], th[3]};
                uint32_t bl0[2] = {tl[0], tl[2]}, bl1[2] = {tl[1], tl[3]};
#pragma unroll
                for (int mi = 0; mi < 2; mi++) {
                    mma_bf16(acc[mi][np * 2 + 0], ah[mi], bh0);
                    mma_bf16(acc[mi][np * 2 + 0], ah[mi], bl0);
                    mma_bf16(acc[mi][np * 2 + 0], al[mi], bh0);
                    mma_bf16(acc[mi][np * 2 + 1], ah[mi], bh1);
                    mma_bf16(acc[mi][np * 2 + 1], ah[mi], bl1);
                    mma_bf16(acc[mi][np * 2 + 1], al[mi], bh1);
                }
            }
        }
    }

    int r_in = lane >> 2;
    int c_in = (lane & 3) * 2;
#pragma unroll
    for (int mi = 0; mi < 2; mi++)
#pragma unroll
        for (int half = 0; half < 2; half++) {
            int gr = base_row + m_warp + mi * 16 + r_in + half * 8;
            if (gr >= n) continue;
#pragma unroll
            for (int ni = 0; ni < 8; ni++) {
                int col = n_warp + ni * 8 + c_in;
                float y0 = fmaxf(acc[mi][ni][half * 2 + 0] + __ldg(bias + col + 0), 0.f);
                float y1 = fmaxf(acc[mi][ni][half * 2 + 1] + __ldg(bias + col + 1), 0.f);
                *(float2*)(outF + (size_t)gr * FD + col) = make_float2(y0, y1);
            }
        }
}

// ---- fused layers 2+3 (verbatim from R8): 512 threads ----------------------
#define PS   136
#define BUFB (128 * PS * 2)
#define G2_AH 0
#define G2_AL (BUFB)
#define G2_W2H (2 * BUFB)
#define G2_W2L (3 * BUFB)
#define G2_W3H (4 * BUFB)
#define G2_W3L (5 * BUFB)
#define G2_SMEM (6 * BUFB)

__global__ void __launch_bounds__(512, 1)
gemm23(const float* __restrict__ Aagg, const float* __restrict__ Aself,
       const __nv_bfloat16* __restrict__ W2hi, const __nv_bfloat16* __restrict__ W2lo,
       const __nv_bfloat16* __restrict__ W3hi, const __nv_bfloat16* __restrict__ W3lo,
       const float* __restrict__ b2, const float* __restrict__ b3,
       float* __restrict__ out1, float* __restrict__ out2, int n) {
    extern __shared__ __align__(16) char smem[];
    uint32_t sb = smem_u32(smem);
    int tid = threadIdx.x, wid = tid >> 5, lane = tid & 31;
    int base_row = blockIdx.x * 128;

    int layer = wid >> 3;
    int m_warp = (wid & 3) * 32;
    int n_warp = ((wid >> 2) & 1) * 64;
    uint32_t offWH = layer ? G2_W3H : G2_W2H;
    uint32_t offWL = layer ? G2_W3L : G2_W2L;

    float acc[2][8][4];
#pragma unroll
    for (int i = 0; i < 2; i++)
#pragma unroll
        for (int j = 0; j < 8; j++)
#pragma unroll
            for (int k = 0; k < 4; k++) acc[i][j][k] = 0.0f;

    int g = lane >> 3, lr = lane & 7;
    int a_row = (g & 1) * 8 + lr;
    int a_col = (g >> 1) * 8;

    for (int kc = 0; kc < 2; kc++) {
        if (kc) __syncthreads();
        const float* S = kc ? Aself : Aagg;
#pragma unroll
        for (int i = 0; i < 8; i++) {
            int q = tid + i * 512;
            int row = q >> 5;
            int c4 = (q & 31) << 2;
            int gr = base_row + row;
            float4 v = (gr < n) ? __ldg((const float4*)(S + (size_t)gr * FD + c4))
                                : make_float4(0.f, 0.f, 0.f, 0.f);
            uint32_t h0, l0, h1, l1;
            split2(v.x, v.y, h0, l0);
            split2(v.z, v.w, h1, l1);
            uint32_t so = (uint32_t)(row * PS + c4) * 2;
            *(uint2*)(smem + G2_AH + so) = make_uint2(h0, h1);
            *(uint2*)(smem + G2_AL + so) = make_uint2(l0, l1);
        }
#pragma unroll
        for (int i = 0; i < 4; i++) {
            int q = tid + i * 512;
            int row = q >> 4;
            int c8 = (q & 15) * 8;
            size_t gW = (size_t)row * 256 + kc * 128 + c8;
            uint32_t so = (uint32_t)(row * PS + c8) * 2;
            *(uint4*)(smem + G2_W2H + so) = *(const uint4*)(W2hi + gW);
            *(uint4*)(smem + G2_W2L + so) = *(const uint4*)(W2lo + gW);
            *(uint4*)(smem + G2_W3H + so) = *(const uint4*)(W3hi + gW);
            *(uint4*)(smem + G2_W3L + so) = *(const uint4*)(W3lo + gW);
        }
        __syncthreads();

#pragma unroll
        for (int k16 = 0; k16 < 8; k16++) {
            int kb = k16 * 16;
            uint32_t ah[2][4], al[2][4];
#pragma unroll
            for (int mi = 0; mi < 2; mi++) {
                uint32_t ad = sb + (uint32_t)((m_warp + mi * 16 + a_row) * PS + kb + a_col) * 2;
                ldm_x4(ah[mi], G2_AH + ad);
                ldm_x4(al[mi], G2_AL + ad);
            }
            uint32_t bh[8][2], bl[8][2];
#pragma unroll
            for (int np = 0; np < 4; np++) {
                uint32_t bd = sb + (uint32_t)((n_warp + np * 16 + a_row) * PS + kb + a_col) * 2;
                uint32_t t[4];
                ldm_x4(t, offWH + bd);
                bh[np * 2 + 0][0] = t[0]; bh[np * 2 + 0][1] = t[2];
                bh[np * 2 + 1][0] = t[1]; bh[np * 2 + 1][1] = t[3];
                ldm_x4(t, offWL + bd);
                bl[np * 2 + 0][0] = t[0]; bl[np * 2 + 0][1] = t[2];
                bl[np * 2 + 1][0] = t[1]; bl[np * 2 + 1][1] = t[3];
            }
#pragma unroll
            for (int mi = 0; mi < 2; mi++)
#pragma unroll
                for (int ni = 0; ni < 8; ni++) {
                    mma_bf16(acc[mi][ni], ah[mi], bh[ni]);
                    mma_bf16(acc[mi][ni], ah[mi], bl[ni]);
                    mma_bf16(acc[mi][ni], al[mi], bh[ni]);
                }
        }
    }

    const float* bias = layer ? b3 : b2;
    float* outF = layer ? out2 : out1;
    int r_in = lane >> 2;
    int c_in = (lane & 3) * 2;
#pragma unroll
    for (int mi = 0; mi < 2; mi++)
#pragma unroll
        for (int half = 0; half < 2; half++) {
            int gr = base_row + m_warp + mi * 16 + r_in + half * 8;
            if (gr >= n) continue;
#pragma unroll
            for (int ni = 0; ni < 8; ni++) {
                int col = n_warp + ni * 8 + c_in;
                float y0 = acc[mi][ni][half * 2 + 0] + __ldg(bias + col + 0);
                float y1 = acc[mi][ni][half * 2 + 1] + __ldg(bias + col + 1);
                *(float2*)(outF + (size_t)gr * FD + col) = make_float2(y0, y1);
            }
        }
}

// ---------------- launch ----------------------------------------------------
extern "C" void kernel_launch(void* const* d_in, const int* in_sizes, int n_in,
                              void* d_out, int out_size) {
    const float* x   = (const float*)d_in[0];
    const int*   ei  = (const int*)d_in[1];
    const float* W1l = (const float*)d_in[2];
    const float* b1l = (const float*)d_in[3];
    const float* W1r = (const float*)d_in[4];
    const float* W2l = (const float*)d_in[5];
    const float* b2l = (const float*)d_in[6];
    const float* W2r = (const float*)d_in[7];
    const float* W3l = (const float*)d_in[8];
    const float* b3l = (const float*)d_in[9];
    const float* W3r = (const float*)d_in[10];

    int n = in_sizes[0] / FD;
    int E = in_sizes[1] / 2;
    const int* src = ei;
    const int* dst = ei + E;

    float* out_h1 = (float*)d_out;
    float* out_h2 = (float*)d_out + (size_t)n * FD;

    void *pa1 = 0, *pa2 = 0, *px1 = 0, *pwh = 0, *pwl = 0;
    cudaGetSymbolAddress(&pa1, g_agg1);
    cudaGetSymbolAddress(&pa2, g_agg2);
    cudaGetSymbolAddress(&px1, g_x1);
    cudaGetSymbolAddress(&pwh, g_wh);
    cudaGetSymbolAddress(&pwl, g_wl);
    float* agg1 = (float*)pa1;
    float* agg2 = (float*)pa2;
    float* x1   = (float*)px1;
    __nv_bfloat16* wh = (__nv_bfloat16*)pwh;
    __nv_bfloat16* wl = (__nv_bfloat16*)pwl;

    cudaFuncSetAttribute(gemm1,  cudaFuncAttributeMaxDynamicSharedMemorySize, Q1_SMEM);
    cudaFuncSetAttribute(gemm23, cudaFuncAttributeMaxDynamicSharedMemorySize, G2_SMEM);

    int nblocks256 = (n + 255) / 256;
    int eblocks = (E + 255) / 256;
    int gabl = (n * 32 + 255) / 256;
    int gblocks = (n + 127) / 128;

    // CSR build (5 launches)
    zero_cnt<<<nblocks256, 256>>>(n);
    hist_kernel<<<eblocks, 256>>>(dst, E, n);
    offsets2_kernel<<<nblocks256, 256>>>(n);
    fill_kernel<<<eblocks, 256>>>(src, dst, E, n);
    conv_w<<<(3 * 128 * 64 + 255) / 256, 256>>>(W1l, W1r, W2l, W2r, W3l, W3r);

    // layer 1
    gather_kernel<<<gabl, 256>>>(x, agg1, n);
    gemm1<<<gblocks, 256, Q1_SMEM>>>(agg1, x, wh, wl, b1l, x1, n);

    // layers 2 + 3
    gather_kernel<<<gabl, 256>>>(x1, agg2, n);
    gemm23<<<gblocks, 512, G2_SMEM>>>(agg2, x1,
                                      wh + 32768, wl + 32768,
                                      wh + 65536, wl + 65536,
                                      b2l, b3l, out_h1, out_h2, n);
}